// round 4
// baseline (speedup 1.0000x reference)
#include <cuda_runtime.h>
#include <cuda_bf16.h>
#include <cstdint>

// ---------------------------------------------------------------------------
// Problem constants
// ---------------------------------------------------------------------------
#define BB    16
#define TT    2048
#define DIM   1024
#define NST   64
#define MTOT  (BB * TT)          // 32768 rows

// ---------------------------------------------------------------------------
// Scratch (__device__ globals — no allocation allowed)
// ---------------------------------------------------------------------------
__device__ float g_xp  [(size_t)MTOT * DIM];   // 128 MB : silu(x @ W_in^T)
__device__ float g_kvqa[(size_t)MTOT * 256];   //  32 MB : [m][k|v|q|ax] (64 each)
__device__ float g_cell[(size_t)MTOT * NST];   //   8 MB : gated cell output
__device__ float g_wcat[(size_t)256 * DIM];    //   1 MB : concat(W_k,W_v,W_q,W_alpha)

// ---------------------------------------------------------------------------
// Small helpers
// ---------------------------------------------------------------------------
__device__ __forceinline__ float fast_sigmoid(float x) {
    return __fdividef(1.0f, 1.0f + __expf(-x));
}

__device__ __forceinline__ void ffma2(unsigned long long &acc,
                                      unsigned long long a,
                                      unsigned long long b) {
    asm("fma.rn.f32x2 %0, %1, %2, %0;" : "+l"(acc) : "l"(a), "l"(b));
}

__device__ __forceinline__ unsigned long long splat2(float v) {
    unsigned long long r;
    asm("mov.b64 %0, {%1, %1};" : "=l"(r) : "r"(__float_as_uint(v)));
    return r;
}

// ---------------------------------------------------------------------------
// Kernel 0: concatenate the four projection weights into [256][1024]
// ---------------------------------------------------------------------------
__global__ void concat_w_kernel(const float* __restrict__ Wk,
                                const float* __restrict__ Wv,
                                const float* __restrict__ Wq,
                                const float* __restrict__ Wa,
                                float* __restrict__ out) {
    int i = blockIdx.x * blockDim.x + threadIdx.x;   // 0 .. 256*1024-1
    if (i >= 256 * DIM) return;
    int n = i >> 10;
    int d = i & (DIM - 1);
    const float* src = (n < 64) ? Wk : (n < 128) ? Wv : (n < 192) ? Wq : Wa;
    out[i] = src[(n & 63) * DIM + d];
}

// ---------------------------------------------------------------------------
// Kernel 1/2/4: fp32 SGEMM  C[M,N] = A[M,K] * B[N,K]^T   (both K-major)
// 128x128 tile, BK=8, 256 threads, 8x8 microtile, FFMA2 accumulators,
// smem double-buffered via register-staged global loads.
// Optional fused SiLU epilogue.
// ---------------------------------------------------------------------------
template <bool SILU>
__global__ __launch_bounds__(256, 2)
void sgemm_kernel(const float* __restrict__ A,
                  const float* __restrict__ B,
                  float* __restrict__ C,
                  int M, int N, int K) {
    __shared__ float As[2][8][128];
    __shared__ float Bs[2][8][128];

    const int tid = threadIdx.x;
    const int tx  = tid & 15;          // 0..15 -> column group
    const int ty  = tid >> 4;          // 0..15 -> row group
    const int bm0 = blockIdx.y * 128;
    const int bn0 = blockIdx.x * 128;

    const int lr = tid >> 1;           // 0..127 : tile-local load row
    const int lk = (tid & 1) * 4;      // 0 or 4 : k offset within BK

    const float* Aptr = A + (size_t)(bm0 + lr) * K + lk;
    const float* Bptr = B + (size_t)(bn0 + lr) * K + lk;

    unsigned long long acc[8][4];
#pragma unroll
    for (int i = 0; i < 8; i++)
#pragma unroll
        for (int j = 0; j < 4; j++) acc[i][j] = 0ULL;

    const int NIT = K >> 3;

    // prologue: tile 0
    {
        float4 av = *(const float4*)Aptr;
        float4 bv = *(const float4*)Bptr;
        As[0][lk + 0][lr] = av.x; As[0][lk + 1][lr] = av.y;
        As[0][lk + 2][lr] = av.z; As[0][lk + 3][lr] = av.w;
        Bs[0][lk + 0][lr] = bv.x; Bs[0][lk + 1][lr] = bv.y;
        Bs[0][lk + 2][lr] = bv.z; Bs[0][lk + 3][lr] = bv.w;
    }
    __syncthreads();

    int buf = 0;
    for (int it = 0; it < NIT; ++it) {
        float4 an, bn_;
        const bool pf = (it + 1 < NIT);
        if (pf) {
            an  = *(const float4*)(Aptr + (size_t)(it + 1) * 8);
            bn_ = *(const float4*)(Bptr + (size_t)(it + 1) * 8);
        }
#pragma unroll
        for (int k = 0; k < 8; k++) {
            float4 a0 = *(const float4*)&As[buf][k][ty * 4];
            float4 a1 = *(const float4*)&As[buf][k][ty * 4 + 64];
            float4 b0 = *(const float4*)&Bs[buf][k][tx * 4];
            float4 b1 = *(const float4*)&Bs[buf][k][tx * 4 + 64];
            unsigned long long bp[4];
            bp[0] = ((const unsigned long long*)&b0)[0];
            bp[1] = ((const unsigned long long*)&b0)[1];
            bp[2] = ((const unsigned long long*)&b1)[0];
            bp[3] = ((const unsigned long long*)&b1)[1];
            float ar[8] = {a0.x, a0.y, a0.z, a0.w, a1.x, a1.y, a1.z, a1.w};
#pragma unroll
            for (int i = 0; i < 8; i++) {
                unsigned long long ap = splat2(ar[i]);
#pragma unroll
                for (int j = 0; j < 4; j++) ffma2(acc[i][j], ap, bp[j]);
            }
        }
        if (pf) {
            int nb = buf ^ 1;
            As[nb][lk + 0][lr] = an.x;  As[nb][lk + 1][lr] = an.y;
            As[nb][lk + 2][lr] = an.z;  As[nb][lk + 3][lr] = an.w;
            Bs[nb][lk + 0][lr] = bn_.x; Bs[nb][lk + 1][lr] = bn_.y;
            Bs[nb][lk + 2][lr] = bn_.z; Bs[nb][lk + 3][lr] = bn_.w;
        }
        __syncthreads();
        buf ^= 1;
    }

    // epilogue
#pragma unroll
    for (int i = 0; i < 8; i++) {
        int rloc = (i < 4) ? (ty * 4 + i) : (64 + ty * 4 + (i - 4));
        int m = bm0 + rloc;
        float v[8];
#pragma unroll
        for (int j = 0; j < 4; j++) {
            v[2 * j]     = __uint_as_float((unsigned)(acc[i][j]));
            v[2 * j + 1] = __uint_as_float((unsigned)(acc[i][j] >> 32));
        }
        if (SILU) {
#pragma unroll
            for (int j = 0; j < 8; j++) v[j] = v[j] * fast_sigmoid(v[j]);
        }
        float* cp = C + (size_t)m * N + bn0;
        *(float4*)(cp + tx * 4)      = make_float4(v[0], v[1], v[2], v[3]);
        *(float4*)(cp + 64 + tx * 4) = make_float4(v[4], v[5], v[6], v[7]);
    }
}

// ---------------------------------------------------------------------------
// Kernel 3: the sequential gated scan.
// One CTA per batch (16 CTAs), 128 threads: thread t owns row r=t>>1,
// half h=t&1 -> columns [h*32, h*32+32) of S (32 fp32 registers).
// k/v/q/ax streamed through smem in cp.async double-buffered 16-step chunks.
// Per step: retrieved = S.k (warp shuffle pair-reduce), alpha = sigmoid(...),
// S = a*S + (1-a)*v*k, o = S.q, out = o*silu(o).
// ---------------------------------------------------------------------------
#define SCAN_CH 16

__global__ __launch_bounds__(128, 1)
void scan_kernel(const float* __restrict__ kvqa,
                 const float* __restrict__ d_alpha,
                 const float* __restrict__ b_alpha,
                 float* __restrict__ cell,
                 float* __restrict__ S_out) {
    __shared__ float buf[2][SCAN_CH * 256];
    __shared__ float osm[SCAN_CH * 64];

    const int b   = blockIdx.x;
    const int tid = threadIdx.x;
    const int r   = tid >> 1;
    const int h   = tid & 1;
    const int c0  = h * 32;

    float S[32];
#pragma unroll
    for (int j = 0; j < 32; j++) S[j] = 0.0f;

    const float dA = d_alpha[r];
    const float bA = b_alpha[r];

    const float* gsrc = kvqa + (size_t)b * TT * 256;

    // prologue: chunk 0 -> buf[0]
    {
        unsigned sa = (unsigned)__cvta_generic_to_shared(&buf[0][0]);
        const float* g = gsrc;
        for (int i = tid; i < SCAN_CH * 64; i += 128)
            asm volatile("cp.async.cg.shared.global [%0], [%1], 16;"
                         :: "r"(sa + i * 16), "l"(g + (size_t)i * 4));
        asm volatile("cp.async.commit_group;");
    }

    const int NCH = TT / SCAN_CH;   // 128
    for (int c = 0; c < NCH; ++c) {
        asm volatile("cp.async.wait_group 0;");
        __syncthreads();

        if (c + 1 < NCH) {
            unsigned sa = (unsigned)__cvta_generic_to_shared(&buf[(c + 1) & 1][0]);
            const float* g = gsrc + (size_t)(c + 1) * SCAN_CH * 256;
            for (int i = tid; i < SCAN_CH * 64; i += 128)
                asm volatile("cp.async.cg.shared.global [%0], [%1], 16;"
                             :: "r"(sa + i * 16), "l"(g + (size_t)i * 4));
            asm volatile("cp.async.commit_group;");
        }

        const float* cb = &buf[c & 1][0];
#pragma unroll 1
        for (int s = 0; s < SCAN_CH; ++s) {
            const float* p = cb + s * 256;

            float4 k4[8];
            const float4* kp = (const float4*)(p + c0);
#pragma unroll
            for (int i = 0; i < 8; i++) k4[i] = kp[i];

            // retrieved_r = sum_j S[r][j] * k[j]
            float r0 = 0.f, r1 = 0.f, r2 = 0.f, r3 = 0.f;
#pragma unroll
            for (int i = 0; i < 8; i++) {
                r0 = fmaf(S[4 * i + 0], k4[i].x, r0);
                r1 = fmaf(S[4 * i + 1], k4[i].y, r1);
                r2 = fmaf(S[4 * i + 2], k4[i].z, r2);
                r3 = fmaf(S[4 * i + 3], k4[i].w, r3);
            }
            float rp = (r0 + r1) + (r2 + r3);
            rp += __shfl_xor_sync(0xffffffffu, rp, 1);

            float axv = p[192 + r];
            float vv  = p[64 + r];
            float araw = fmaf(dA, rp, axv + bA);
            float al   = fast_sigmoid(araw);
            float cc   = (1.0f - al) * vv;

            // fused update + o = S_new . q
            float o0 = 0.f, o1 = 0.f, o2 = 0.f, o3 = 0.f;
            const float4* qp = (const float4*)(p + 128 + c0);
#pragma unroll
            for (int i = 0; i < 8; i++) {
                float4 q4 = qp[i];
                S[4 * i + 0] = fmaf(al, S[4 * i + 0], cc * k4[i].x);
                S[4 * i + 1] = fmaf(al, S[4 * i + 1], cc * k4[i].y);
                S[4 * i + 2] = fmaf(al, S[4 * i + 2], cc * k4[i].z);
                S[4 * i + 3] = fmaf(al, S[4 * i + 3], cc * k4[i].w);
                o0 = fmaf(S[4 * i + 0], q4.x, o0);
                o1 = fmaf(S[4 * i + 1], q4.y, o1);
                o2 = fmaf(S[4 * i + 2], q4.z, o2);
                o3 = fmaf(S[4 * i + 3], q4.w, o3);
            }
            float o = (o0 + o1) + (o2 + o3);
            o += __shfl_xor_sync(0xffffffffu, o, 1);

            if (h == 0) {
                float sg = fast_sigmoid(o);
                osm[s * 64 + r] = o * o * sg;   // o * silu(o)
            }
        }
        __syncthreads();

        // dump chunk outputs
        {
            float* gout = cell + ((size_t)b * TT + (size_t)c * SCAN_CH) * NST;
            const float4* src4 = (const float4*)osm;
            float4* dst4 = (float4*)gout;
            for (int i = tid; i < SCAN_CH * 16; i += 128) dst4[i] = src4[i];
        }
    }

    // S_final -> tail of d_out
    float* sp = S_out + (size_t)b * (NST * NST) + (size_t)r * NST + c0;
#pragma unroll
    for (int i = 0; i < 8; i++)
        ((float4*)sp)[i] = make_float4(S[4 * i + 0], S[4 * i + 1],
                                       S[4 * i + 2], S[4 * i + 3]);
}

// ---------------------------------------------------------------------------
// Launch
// ---------------------------------------------------------------------------
extern "C" void kernel_launch(void* const* d_in, const int* in_sizes, int n_in,
                              void* d_out, int out_size) {
    const float* x   = (const float*)d_in[0];
    const float* Win = (const float*)d_in[1];
    const float* Wk  = (const float*)d_in[2];
    const float* Wv  = (const float*)d_in[3];
    const float* Wq  = (const float*)d_in[4];
    const float* Wa  = (const float*)d_in[5];
    const float* dAl = (const float*)d_in[6];
    const float* bAl = (const float*)d_in[7];
    const float* Wout= (const float*)d_in[8];
    float* out = (float*)d_out;

    void *xp_v, *kvqa_v, *cell_v, *wcat_v;
    cudaGetSymbolAddress(&xp_v,   g_xp);
    cudaGetSymbolAddress(&kvqa_v, g_kvqa);
    cudaGetSymbolAddress(&cell_v, g_cell);
    cudaGetSymbolAddress(&wcat_v, g_wcat);
    float* xp   = (float*)xp_v;
    float* kvqa = (float*)kvqa_v;
    float* cell = (float*)cell_v;
    float* wcat = (float*)wcat_v;

    // 0) concat projection weights
    concat_w_kernel<<<(256 * DIM + 255) / 256, 256>>>(Wk, Wv, Wq, Wa, wcat);

    // 1) xp = silu(x @ W_in^T)   [32768,1024] x [1024,1024]
    sgemm_kernel<true><<<dim3(DIM / 128, MTOT / 128), 256>>>(
        x, Win, xp, MTOT, DIM, DIM);

    // 2) kvqa = xp @ Wcat^T      [32768,1024] x [256,1024]
    sgemm_kernel<false><<<dim3(256 / 128, MTOT / 128), 256>>>(
        xp, wcat, kvqa, MTOT, 256, DIM);

    // 3) sequential gated scan (also writes S_final to tail of d_out)
    scan_kernel<<<BB, 128>>>(kvqa, dAl, bAl, cell,
                             out + (size_t)MTOT * DIM);

    // 4) output = cell @ W_out^T  [32768,64] x [1024,64]
    sgemm_kernel<false><<<dim3(DIM / 128, MTOT / 128), 256>>>(
        cell, Wout, out, MTOT, DIM, NST);
}

// round 6
// speedup vs baseline: 1.2238x; 1.2238x over previous
#include <cuda_runtime.h>
#include <cuda_fp16.h>
#include <cuda_bf16.h>
#include <cstdint>

// ---------------------------------------------------------------------------
// Problem constants
// ---------------------------------------------------------------------------
#define BB    16
#define TT    2048
#define DIM   1024
#define NST   64
#define MTOT  (BB * TT)          // 32768 rows

// HMMA GEMM tiling
#define BM    128
#define BN    128
#define BK    16
#define LDSK  24                 // padded halves per smem row (48B -> conflict-free)
#define TILE_B (128 * LDSK * 2)  // 6144 B per operand tile
#define STG_B  (4 * TILE_B)      // 24576 B per stage (Ah,Al,Bh,Bl)
#define SMEM_H (3 * STG_B)       // 73728 B (3 stages)

// ---------------------------------------------------------------------------
// Scratch (__device__ globals — no allocation allowed)
// ---------------------------------------------------------------------------
__device__ __align__(16) __half g_xhh[(size_t)MTOT * DIM];  // x hi
__device__ __align__(16) __half g_xhl[(size_t)MTOT * DIM];  // x lo
__device__ __align__(16) __half g_xph[(size_t)MTOT * DIM];  // xp hi
__device__ __align__(16) __half g_xpl[(size_t)MTOT * DIM];  // xp lo
__device__ __align__(16) __half g_wih[(size_t)DIM * DIM];   // W_in hi
__device__ __align__(16) __half g_wil[(size_t)DIM * DIM];   // W_in lo
__device__ __align__(16) __half g_wch[(size_t)256 * DIM];   // wcat hi
__device__ __align__(16) __half g_wcl[(size_t)256 * DIM];   // wcat lo
__device__ float g_kvqa[(size_t)MTOT * 256];   // 32 MB : [m][k|v|q|ax]
__device__ float g_cell[(size_t)MTOT * NST];   //  8 MB : gated cell output

// ---------------------------------------------------------------------------
// Helpers
// ---------------------------------------------------------------------------
__device__ __forceinline__ float fast_sigmoid(float x) {
    return __fdividef(1.0f, 1.0f + __expf(-x));
}

__device__ __forceinline__ uint32_t smem_u32(const void* p) {
    uint32_t a;
    asm("{ .reg .u64 t; cvta.to.shared.u64 t, %1; cvt.u32.u64 %0, t; }"
        : "=r"(a) : "l"(p));
    return a;
}

__device__ __forceinline__ void cp16(uint32_t dst, const void* src) {
    asm volatile("cp.async.cg.shared.global [%0], [%1], 16;"
                 :: "r"(dst), "l"(src));
}

__device__ __forceinline__ uint32_t lds32(uint32_t a) {
    uint32_t v;
    asm("ld.shared.b32 %0, [%1];" : "=r"(v) : "r"(a));
    return v;
}

__device__ __forceinline__ void mma16816(float* c, const uint32_t* a,
                                         const uint32_t* b) {
    asm volatile(
        "mma.sync.aligned.m16n8k16.row.col.f32.f16.f16.f32 "
        "{%0,%1,%2,%3}, {%4,%5,%6,%7}, {%8,%9}, {%0,%1,%2,%3};"
        : "+f"(c[0]), "+f"(c[1]), "+f"(c[2]), "+f"(c[3])
        : "r"(a[0]), "r"(a[1]), "r"(a[2]), "r"(a[3]), "r"(b[0]), "r"(b[1]));
}

__device__ __forceinline__ void ffma2(unsigned long long &acc,
                                      unsigned long long a,
                                      unsigned long long b) {
    asm("fma.rn.f32x2 %0, %1, %2, %0;" : "+l"(acc) : "l"(a), "l"(b));
}
__device__ __forceinline__ unsigned long long splat2(float v) {
    unsigned long long r;
    asm("mov.b64 %0, {%1, %1};" : "=l"(r) : "r"(__float_as_uint(v)));
    return r;
}

__device__ __forceinline__ void split_hl(float v, __half& h, __half& l) {
    h = __float2half_rn(v);
    l = __float2half_rn(v - __half2float(h));
}

// ---------------------------------------------------------------------------
// Conversion kernels: fp32 -> fp16 hi/lo, row-major, 8 elems per thread
// ---------------------------------------------------------------------------
__global__ void conv_hl_kernel(const float* __restrict__ src,
                               __half* __restrict__ hi,
                               __half* __restrict__ lo, int n8) {
    int t = blockIdx.x * blockDim.x + threadIdx.x;
    if (t >= n8) return;
    const float4* s = (const float4*)(src + (size_t)t * 8);
    float4 a = s[0], b = s[1];
    float v[8] = {a.x, a.y, a.z, a.w, b.x, b.y, b.z, b.w};
    __half hv[8], lv[8];
#pragma unroll
    for (int i = 0; i < 8; i++) split_hl(v[i], hv[i], lv[i]);
    *(uint4*)(hi + (size_t)t * 8) = *(uint4*)hv;
    *(uint4*)(lo + (size_t)t * 8) = *(uint4*)lv;
}

// wcat = concat(W_k,W_v,W_q,W_alpha)[256][1024] -> hi/lo
__global__ void conv_wcat_kernel(const float* __restrict__ Wk,
                                 const float* __restrict__ Wv,
                                 const float* __restrict__ Wq,
                                 const float* __restrict__ Wa,
                                 __half* __restrict__ hi,
                                 __half* __restrict__ lo) {
    int t = blockIdx.x * blockDim.x + threadIdx.x;   // 32768 threads
    if (t >= 256 * DIM / 8) return;
    int e0 = t * 8;
    int n = e0 >> 10;
    int j = e0 & 1023;
    const float* src = (n < 64) ? Wk : (n < 128) ? Wv : (n < 192) ? Wq : Wa;
    const float4* s = (const float4*)(src + (size_t)(n & 63) * DIM + j);
    float4 a = s[0], b = s[1];
    float v[8] = {a.x, a.y, a.z, a.w, b.x, b.y, b.z, b.w};
    __half hv[8], lv[8];
#pragma unroll
    for (int i = 0; i < 8; i++) split_hl(v[i], hv[i], lv[i]);
    *(uint4*)(hi + (size_t)e0) = *(uint4*)hv;
    *(uint4*)(lo + (size_t)e0) = *(uint4*)lv;
}

// ---------------------------------------------------------------------------
// HMMA GEMM: C[M,N] = A[M,K] * B[N,K]^T, fp16 hi/lo 3-term split, fp32 accum.
// A,B row-major [rows][K] fp16 (hi & lo tensors). 256 thr, 8 warps (2x4),
// warp tile 64x32, BK=16, 3-stage cp.async pipeline.
// EPI 0: write fp32 C. EPI 1: silu epilogue, write fp16 hi/lo (for next GEMM).
// ---------------------------------------------------------------------------
template <int EPI>
__global__ __launch_bounds__(256, 2)
void hgemm_kernel(const __half* __restrict__ Ahg,
                  const __half* __restrict__ Alg,
                  const __half* __restrict__ Bhg,
                  const __half* __restrict__ Blg,
                  float* __restrict__ Cf,
                  __half* __restrict__ Oh,
                  __half* __restrict__ Ol,
                  int N, int K) {
    extern __shared__ __align__(16) __half hsm[];
    const int tid  = threadIdx.x;
    const int wid  = tid >> 5, lane = tid & 31;
    const int wm   = wid >> 2, wn = wid & 3;          // 2 x 4 warp grid
    const int gr   = lane >> 2, gc2 = (lane & 3) * 2;
    const int bm0  = blockIdx.y * BM;
    const int bn0  = blockIdx.x * BN;

    const __half* gAh = Ahg + (size_t)bm0 * K;
    const __half* gAl = Alg + (size_t)bm0 * K;
    const __half* gBh = Bhg + (size_t)bn0 * K;
    const __half* gBl = Blg + (size_t)bn0 * K;

    const uint32_t smu = smem_u32(hsm);

    float acc[4][4][4];
#pragma unroll
    for (int mi = 0; mi < 4; mi++)
#pragma unroll
        for (int ni = 0; ni < 4; ni++)
#pragma unroll
            for (int j = 0; j < 4; j++) acc[mi][ni][j] = 0.0f;

    const int NKT = K >> 4;   // 64

    // loader: stage s <- k-tile kt.  1024 cp.async of 16B; 4 per thread.
    auto load_stage = [&](int s, int kt) {
        uint32_t sb = smu + s * STG_B;
        const __half* bases[4] = {gAh, gAl, gBh, gBl};
#pragma unroll
        for (int j = 0; j < 4; j++) {
            int c   = tid + j * 256;       // 0..1023
            int t   = c >> 8;              // tile 0..3
            int idx = c & 255;
            int row = idx >> 1, ch = idx & 1;
            const __half* gp = bases[t] + (size_t)row * K + kt * BK + ch * 8;
            uint32_t dp = sb + t * TILE_B + (row * LDSK + ch * 8) * 2;
            cp16(dp, gp);
        }
    };

    load_stage(0, 0);
    asm volatile("cp.async.commit_group;");
    load_stage(1, 1);
    asm volatile("cp.async.commit_group;");

    for (int kt = 0; kt < NKT; kt++) {
        asm volatile("cp.async.wait_group 1;");
        __syncthreads();

        if (kt + 2 < NKT) load_stage((kt + 2) % 3, kt + 2);
        asm volatile("cp.async.commit_group;");

        // ---- compute stage kt%3 (one k16) ----
        uint32_t sA  = smu + (kt % 3) * STG_B;
        uint32_t sAl = sA + TILE_B;
        uint32_t sBh = sA + 2 * TILE_B;
        uint32_t sBl = sA + 3 * TILE_B;

        uint32_t a[4][4], bh[4][2], bl[4][2];
#pragma unroll
        for (int mi = 0; mi < 4; mi++) {
            uint32_t base = sA + ((wm * 64 + mi * 16 + gr) * LDSK + gc2) * 2;
            a[mi][0] = lds32(base);
            a[mi][1] = lds32(base + 8 * LDSK * 2);
            a[mi][2] = lds32(base + 16);
            a[mi][3] = lds32(base + 8 * LDSK * 2 + 16);
        }
#pragma unroll
        for (int ni = 0; ni < 4; ni++) {
            uint32_t off = ((wn * 32 + ni * 8 + gr) * LDSK + gc2) * 2;
            bh[ni][0] = lds32(sBh + off);
            bh[ni][1] = lds32(sBh + off + 16);
            bl[ni][0] = lds32(sBl + off);
            bl[ni][1] = lds32(sBl + off + 16);
        }
        // Ah*Bh + Ah*Bl
#pragma unroll
        for (int mi = 0; mi < 4; mi++)
#pragma unroll
            for (int ni = 0; ni < 4; ni++) {
                mma16816(acc[mi][ni], a[mi], bh[ni]);
                mma16816(acc[mi][ni], a[mi], bl[ni]);
            }
        // reload a <- Al, then Al*Bh
#pragma unroll
        for (int mi = 0; mi < 4; mi++) {
            uint32_t base = sAl + ((wm * 64 + mi * 16 + gr) * LDSK + gc2) * 2;
            a[mi][0] = lds32(base);
            a[mi][1] = lds32(base + 8 * LDSK * 2);
            a[mi][2] = lds32(base + 16);
            a[mi][3] = lds32(base + 8 * LDSK * 2 + 16);
        }
#pragma unroll
        for (int mi = 0; mi < 4; mi++)
#pragma unroll
            for (int ni = 0; ni < 4; ni++)
                mma16816(acc[mi][ni], a[mi], bh[ni]);
    }

    // ---- epilogue ----
#pragma unroll
    for (int mi = 0; mi < 4; mi++) {
        int r0 = bm0 + wm * 64 + mi * 16 + gr;
#pragma unroll
        for (int ni = 0; ni < 4; ni++) {
            int col = bn0 + wn * 32 + ni * 8 + gc2;
            float* c = acc[mi][ni];
            if (EPI == 0) {
                *(float2*)&Cf[(size_t)r0 * N + col]       = make_float2(c[0], c[1]);
                *(float2*)&Cf[(size_t)(r0 + 8) * N + col] = make_float2(c[2], c[3]);
            } else {
                float s0 = c[0] * fast_sigmoid(c[0]);
                float s1 = c[1] * fast_sigmoid(c[1]);
                float s2 = c[2] * fast_sigmoid(c[2]);
                float s3 = c[3] * fast_sigmoid(c[3]);
                __half h0, l0, h1, l1, h2, l2, h3, l3;
                split_hl(s0, h0, l0); split_hl(s1, h1, l1);
                split_hl(s2, h2, l2); split_hl(s3, h3, l3);
                __half2 ph0; ph0.x = h0; ph0.y = h1;
                __half2 pl0; pl0.x = l0; pl0.y = l1;
                __half2 ph1; ph1.x = h2; ph1.y = h3;
                __half2 pl1; pl1.x = l2; pl1.y = l3;
                *(__half2*)&Oh[(size_t)r0 * N + col]       = ph0;
                *(__half2*)&Ol[(size_t)r0 * N + col]       = pl0;
                *(__half2*)&Oh[(size_t)(r0 + 8) * N + col] = ph1;
                *(__half2*)&Ol[(size_t)(r0 + 8) * N + col] = pl1;
            }
        }
    }
}

// ---------------------------------------------------------------------------
// GEMM3 (K=64): fp32 FFMA2 SGEMM  C[M,N] = A[M,K] * B[N,K]^T  (proven kernel)
// ---------------------------------------------------------------------------
__global__ __launch_bounds__(256, 2)
void sgemm_kernel(const float* __restrict__ A,
                  const float* __restrict__ B,
                  float* __restrict__ C,
                  int M, int N, int K) {
    __shared__ float As[2][8][128];
    __shared__ float Bs[2][8][128];

    const int tid = threadIdx.x;
    const int tx  = tid & 15;
    const int ty  = tid >> 4;
    const int bm0 = blockIdx.y * 128;
    const int bn0 = blockIdx.x * 128;
    const int lr = tid >> 1;
    const int lk = (tid & 1) * 4;

    const float* Aptr = A + (size_t)(bm0 + lr) * K + lk;
    const float* Bptr = B + (size_t)(bn0 + lr) * K + lk;

    unsigned long long acc[8][4];
#pragma unroll
    for (int i = 0; i < 8; i++)
#pragma unroll
        for (int j = 0; j < 4; j++) acc[i][j] = 0ULL;

    const int NIT = K >> 3;
    {
        float4 av = *(const float4*)Aptr;
        float4 bv = *(const float4*)Bptr;
        As[0][lk + 0][lr] = av.x; As[0][lk + 1][lr] = av.y;
        As[0][lk + 2][lr] = av.z; As[0][lk + 3][lr] = av.w;
        Bs[0][lk + 0][lr] = bv.x; Bs[0][lk + 1][lr] = bv.y;
        Bs[0][lk + 2][lr] = bv.z; Bs[0][lk + 3][lr] = bv.w;
    }
    __syncthreads();

    int buf = 0;
    for (int it = 0; it < NIT; ++it) {
        float4 an, bn_;
        const bool pf = (it + 1 < NIT);
        if (pf) {
            an  = *(const float4*)(Aptr + (size_t)(it + 1) * 8);
            bn_ = *(const float4*)(Bptr + (size_t)(it + 1) * 8);
        }
#pragma unroll
        for (int k = 0; k < 8; k++) {
            float4 a0 = *(const float4*)&As[buf][k][ty * 4];
            float4 a1 = *(const float4*)&As[buf][k][ty * 4 + 64];
            float4 b0 = *(const float4*)&Bs[buf][k][tx * 4];
            float4 b1 = *(const float4*)&Bs[buf][k][tx * 4 + 64];
            unsigned long long bp[4];
            bp[0] = ((const unsigned long long*)&b0)[0];
            bp[1] = ((const unsigned long long*)&b0)[1];
            bp[2] = ((const unsigned long long*)&b1)[0];
            bp[3] = ((const unsigned long long*)&b1)[1];
            float ar[8] = {a0.x, a0.y, a0.z, a0.w, a1.x, a1.y, a1.z, a1.w};
#pragma unroll
            for (int i = 0; i < 8; i++) {
                unsigned long long ap = splat2(ar[i]);
#pragma unroll
                for (int j = 0; j < 4; j++) ffma2(acc[i][j], ap, bp[j]);
            }
        }
        if (pf) {
            int nb2 = buf ^ 1;
            As[nb2][lk + 0][lr] = an.x;  As[nb2][lk + 1][lr] = an.y;
            As[nb2][lk + 2][lr] = an.z;  As[nb2][lk + 3][lr] = an.w;
            Bs[nb2][lk + 0][lr] = bn_.x; Bs[nb2][lk + 1][lr] = bn_.y;
            Bs[nb2][lk + 2][lr] = bn_.z; Bs[nb2][lk + 3][lr] = bn_.w;
        }
        __syncthreads();
        buf ^= 1;
    }

#pragma unroll
    for (int i = 0; i < 8; i++) {
        int rloc = (i < 4) ? (ty * 4 + i) : (64 + ty * 4 + (i - 4));
        int m = bm0 + rloc;
        float v[8];
#pragma unroll
        for (int j = 0; j < 4; j++) {
            v[2 * j]     = __uint_as_float((unsigned)(acc[i][j]));
            v[2 * j + 1] = __uint_as_float((unsigned)(acc[i][j] >> 32));
        }
        float* cp = C + (size_t)m * N + bn0;
        *(float4*)(cp + tx * 4)      = make_float4(v[0], v[1], v[2], v[3]);
        *(float4*)(cp + 64 + tx * 4) = make_float4(v[4], v[5], v[6], v[7]);
    }
}

// ---------------------------------------------------------------------------
// Sequential gated scan. One CTA per batch, 256 threads: thread t owns
// row r=t>>2, quarter h=t&3 -> 16 columns of S in registers.
// ---------------------------------------------------------------------------
#define SCAN_CH 16

__global__ __launch_bounds__(256, 1)
void scan_kernel(const float* __restrict__ kvqa,
                 const float* __restrict__ d_alpha,
                 const float* __restrict__ b_alpha,
                 float* __restrict__ cell,
                 float* __restrict__ S_out) {
    __shared__ float buf[2][SCAN_CH * 256];
    __shared__ float osm[SCAN_CH * 64];

    const int b   = blockIdx.x;
    const int tid = threadIdx.x;
    const int r   = tid >> 2;
    const int h   = tid & 3;
    const int c0  = h * 16;

    float S[16];
#pragma unroll
    for (int j = 0; j < 16; j++) S[j] = 0.0f;

    const float dA = d_alpha[r];
    const float bA = b_alpha[r];

    const float* gsrc = kvqa + (size_t)b * TT * 256;

    {
        unsigned sa = (unsigned)__cvta_generic_to_shared(&buf[0][0]);
        const float* g = gsrc;
        for (int i = tid; i < SCAN_CH * 64; i += 256)
            asm volatile("cp.async.cg.shared.global [%0], [%1], 16;"
                         :: "r"(sa + i * 16), "l"(g + (size_t)i * 4));
        asm volatile("cp.async.commit_group;");
    }

    const int NCH = TT / SCAN_CH;
    for (int c = 0; c < NCH; ++c) {
        asm volatile("cp.async.wait_group 0;");
        __syncthreads();

        if (c + 1 < NCH) {
            unsigned sa = (unsigned)__cvta_generic_to_shared(&buf[(c + 1) & 1][0]);
            const float* g = gsrc + (size_t)(c + 1) * SCAN_CH * 256;
            for (int i = tid; i < SCAN_CH * 64; i += 256)
                asm volatile("cp.async.cg.shared.global [%0], [%1], 16;"
                             :: "r"(sa + i * 16), "l"(g + (size_t)i * 4));
            asm volatile("cp.async.commit_group;");
        }

        const float* cb = &buf[c & 1][0];
#pragma unroll 1
        for (int s = 0; s < SCAN_CH; ++s) {
            const float* p = cb + s * 256;

            float4 k4[4];
            const float4* kp = (const float4*)(p + c0);
#pragma unroll
            for (int i = 0; i < 4; i++) k4[i] = kp[i];

            float r0 = 0.f, r1 = 0.f, r2 = 0.f, r3 = 0.f;
#pragma unroll
            for (int i = 0; i < 4; i++) {
                r0 = fmaf(S[4 * i + 0], k4[i].x, r0);
                r1 = fmaf(S[4 * i + 1], k4[i].y, r1);
                r2 = fmaf(S[4 * i + 2], k4[i].z, r2);
                r3 = fmaf(S[4 * i + 3], k4[i].w, r3);
            }
            float rp = (r0 + r1) + (r2 + r3);
            rp += __shfl_xor_sync(0xffffffffu, rp, 1);
            rp += __shfl_xor_sync(0xffffffffu, rp, 2);

            float axv = p[192 + r];
            float vv  = p[64 + r];
            float araw = fmaf(dA, rp, axv + bA);
            float al   = fast_sigmoid(araw);
            float cc   = (1.0f - al) * vv;

            float o0 = 0.f, o1 = 0.f, o2 = 0.f, o3 = 0.f;
            const float4* qp = (const float4*)(p + 128 + c0);
#pragma unroll
            for (int i = 0; i < 4; i++) {
                float4 q4 = qp[i];
                S[4 * i + 0] = fmaf(al, S[4 * i + 0], cc * k4[i].x);
                S[4 * i + 1] = fmaf(al, S[4 * i + 1], cc * k4[i].y);
                S[4 * i + 2] = fmaf(al, S[4 * i + 2], cc * k4[i].z);
                S[4 * i + 3] = fmaf(al, S[4 * i + 3], cc * k4[i].w);
                o0 = fmaf(S[4 * i + 0], q4.x, o0);
                o1 = fmaf(S[4 * i + 1], q4.y, o1);
                o2 = fmaf(S[4 * i + 2], q4.z, o2);
                o3 = fmaf(S[4 * i + 3], q4.w, o3);
            }
            float o = (o0 + o1) + (o2 + o3);
            o += __shfl_xor_sync(0xffffffffu, o, 1);
            o += __shfl_xor_sync(0xffffffffu, o, 2);

            if (h == 0) {
                float sg = fast_sigmoid(o);
                osm[s * 64 + r] = o * o * sg;   // o * silu(o)
            }
        }
        __syncthreads();

        {
            float* gout = cell + ((size_t)b * TT + (size_t)c * SCAN_CH) * NST;
            const float4* src4 = (const float4*)osm;
            float4* dst4 = (float4*)gout;
            for (int i = tid; i < SCAN_CH * 16; i += 256) dst4[i] = src4[i];
        }
    }

    float* sp = S_out + (size_t)b * (NST * NST) + (size_t)r * NST + c0;
#pragma unroll
    for (int i = 0; i < 4; i++)
        ((float4*)sp)[i] = make_float4(S[4 * i + 0], S[4 * i + 1],
                                       S[4 * i + 2], S[4 * i + 3]);
}

// ---------------------------------------------------------------------------
// Launch
// ---------------------------------------------------------------------------
extern "C" void kernel_launch(void* const* d_in, const int* in_sizes, int n_in,
                              void* d_out, int out_size) {
    const float* x   = (const float*)d_in[0];
    const float* Win = (const float*)d_in[1];
    const float* Wk  = (const float*)d_in[2];
    const float* Wv  = (const float*)d_in[3];
    const float* Wq  = (const float*)d_in[4];
    const float* Wa  = (const float*)d_in[5];
    const float* dAl = (const float*)d_in[6];
    const float* bAl = (const float*)d_in[7];
    const float* Wout= (const float*)d_in[8];
    float* out = (float*)d_out;

    void *xhh_v, *xhl_v, *xph_v, *xpl_v, *wih_v, *wil_v, *wch_v, *wcl_v,
         *kvqa_v, *cell_v;
    cudaGetSymbolAddress(&xhh_v, g_xhh);  cudaGetSymbolAddress(&xhl_v, g_xhl);
    cudaGetSymbolAddress(&xph_v, g_xph);  cudaGetSymbolAddress(&xpl_v, g_xpl);
    cudaGetSymbolAddress(&wih_v, g_wih);  cudaGetSymbolAddress(&wil_v, g_wil);
    cudaGetSymbolAddress(&wch_v, g_wch);  cudaGetSymbolAddress(&wcl_v, g_wcl);
    cudaGetSymbolAddress(&kvqa_v, g_kvqa);
    cudaGetSymbolAddress(&cell_v, g_cell);
    __half* xhh = (__half*)xhh_v;  __half* xhl = (__half*)xhl_v;
    __half* xph = (__half*)xph_v;  __half* xpl = (__half*)xpl_v;
    __half* wih = (__half*)wih_v;  __half* wil = (__half*)wil_v;
    __half* wch = (__half*)wch_v;  __half* wcl = (__half*)wcl_v;
    float* kvqa = (float*)kvqa_v;
    float* cell = (float*)cell_v;

    cudaFuncSetAttribute(hgemm_kernel<0>,
                         cudaFuncAttributeMaxDynamicSharedMemorySize, SMEM_H);
    cudaFuncSetAttribute(hgemm_kernel<1>,
                         cudaFuncAttributeMaxDynamicSharedMemorySize, SMEM_H);

    // 0) conversions to fp16 hi/lo
    conv_hl_kernel<<<(MTOT * DIM / 8 + 255) / 256, 256>>>(x, xhh, xhl,
                                                          MTOT * DIM / 8);
    conv_hl_kernel<<<(DIM * DIM / 8 + 255) / 256, 256>>>(Win, wih, wil,
                                                         DIM * DIM / 8);
    conv_wcat_kernel<<<(256 * DIM / 8 + 255) / 256, 256>>>(Wk, Wv, Wq, Wa,
                                                           wch, wcl);

    // 1) xp = silu(x @ W_in^T)  (M=32768, N=1024, K=1024) -> fp16 hi/lo
    hgemm_kernel<1><<<dim3(DIM / BN, MTOT / BM), 256, SMEM_H>>>(
        xhh, xhl, wih, wil, nullptr, xph, xpl, DIM, DIM);

    // 2) kvqa = xp @ Wcat^T  (M=32768, N=256, K=1024) -> fp32
    hgemm_kernel<0><<<dim3(256 / BN, MTOT / BM), 256, SMEM_H>>>(
        xph, xpl, wch, wcl, kvqa, nullptr, nullptr, 256, DIM);

    // 3) sequential gated scan (also writes S_final to tail of d_out)
    scan_kernel<<<BB, 256>>>(kvqa, dAl, bAl, cell, out + (size_t)MTOT * DIM);

    // 4) output = cell @ W_out^T  (M=32768, N=1024, K=64)
    sgemm_kernel<<<dim3(DIM / 128, MTOT / 128), 256>>>(
        cell, Wout, out, MTOT, DIM, NST);
}